// round 1
// baseline (speedup 1.0000x reference)
#include <cuda_runtime.h>
#include <math.h>

#define NODES_MAX 100000
#define GRAPHS_MAX 2048

// ---------------- scratch (no allocations allowed) ----------------
__device__ float g_xw [NODES_MAX * 128];   // x @ W (per conv)
__device__ float g_agg[NODES_MAX * 128];   // neighbor aggregation
__device__ float g_h  [NODES_MAX * 128];   // hidden after conv1
__device__ float g_dinv[NODES_MAX];        // rsqrt(deg+1)
__device__ float g_sums[GRAPHS_MAX * 128]; // pooled sums
__device__ float g_cnt [GRAPHS_MAX];       // nodes per graph

__device__ __forceinline__ void red_add_v4(float* addr, float4 v) {
    asm volatile("red.global.add.v4.f32 [%0], {%1,%2,%3,%4};"
                 :: "l"(addr), "f"(v.x), "f"(v.y), "f"(v.z), "f"(v.w)
                 : "memory");
}

// ---------------- zeroing ----------------
__global__ void zero_pre_kernel(int N, int G) {
    int i = blockIdx.x * blockDim.x + threadIdx.x;
    if (i < N * 32) *(float4*)&g_agg[(size_t)i * 4] = make_float4(0.f, 0.f, 0.f, 0.f);
    if (i < G * 32) *(float4*)&g_sums[(size_t)i * 4] = make_float4(0.f, 0.f, 0.f, 0.f);
    if (i < N) g_dinv[i] = 0.f;
    if (i < G) g_cnt[i] = 0.f;
}

__global__ void zero_agg_kernel(int N) {
    int i = blockIdx.x * blockDim.x + threadIdx.x;
    if (i < N * 32) *(float4*)&g_agg[(size_t)i * 4] = make_float4(0.f, 0.f, 0.f, 0.f);
}

// ---------------- degree / counts ----------------
__global__ void deg_kernel(const int* __restrict__ dst, int E) {
    int i = blockIdx.x * blockDim.x + threadIdx.x;
    if (i < E) atomicAdd(&g_dinv[dst[i]], 1.0f);
}

__global__ void cnt_kernel(const int* __restrict__ batch, int N) {
    int i = blockIdx.x * blockDim.x + threadIdx.x;
    if (i < N) atomicAdd(&g_cnt[batch[i]], 1.0f);
}

__global__ void dinv_kernel(int N) {
    int i = blockIdx.x * blockDim.x + threadIdx.x;
    if (i < N) g_dinv[i] = rsqrtf(g_dinv[i] + 1.0f);
}

// ---------------- GEMM: C[M,128] = A[M,128] @ B[128,128], fp32 ----------------
__global__ __launch_bounds__(256) void gemm_n128_kernel(
    const float* __restrict__ A, const float* __restrict__ B,
    float* __restrict__ C, int M)
{
    __shared__ float Xs[64][36];   // padded (stride 36 floats, 16B-aligned rows)
    __shared__ float Ws[32][128];

    int tid = threadIdx.x;
    int tx = tid & 15;        // 16 column groups of 8
    int ty = tid >> 4;        // 16 row groups of 4
    int row0 = blockIdx.x * 64;

    float acc[4][8];
    #pragma unroll
    for (int i = 0; i < 4; i++)
        #pragma unroll
        for (int j = 0; j < 8; j++) acc[i][j] = 0.f;

    for (int kc = 0; kc < 128; kc += 32) {
        // load X tile: 64 rows x 32 cols = 512 float4
        #pragma unroll
        for (int i = 0; i < 2; i++) {
            int idx = tid + i * 256;          // 0..511
            int r = idx >> 3, c4 = idx & 7;   // 8 float4 per row
            float4 v = make_float4(0.f, 0.f, 0.f, 0.f);
            if (row0 + r < M)
                v = *(const float4*)&A[(size_t)(row0 + r) * 128 + kc + c4 * 4];
            *(float4*)&Xs[r][c4 * 4] = v;
        }
        // load W tile: 32 rows x 128 cols = 1024 float4
        #pragma unroll
        for (int i = 0; i < 4; i++) {
            int idx = tid + i * 256;          // 0..1023
            int r = idx >> 5, c4 = idx & 31;
            *(float4*)&Ws[r][c4 * 4] = *(const float4*)&B[(size_t)(kc + r) * 128 + c4 * 4];
        }
        __syncthreads();

        #pragma unroll
        for (int kk = 0; kk < 32; kk++) {
            float a[4];
            #pragma unroll
            for (int i = 0; i < 4; i++) a[i] = Xs[ty * 4 + i][kk];
            float4 b0 = *(float4*)&Ws[kk][tx * 8];
            float4 b1 = *(float4*)&Ws[kk][tx * 8 + 4];
            float b[8] = {b0.x, b0.y, b0.z, b0.w, b1.x, b1.y, b1.z, b1.w};
            #pragma unroll
            for (int i = 0; i < 4; i++)
                #pragma unroll
                for (int j = 0; j < 8; j++)
                    acc[i][j] += a[i] * b[j];
        }
        __syncthreads();
    }

    #pragma unroll
    for (int i = 0; i < 4; i++) {
        int r = row0 + ty * 4 + i;
        if (r < M) {
            float4 o0 = make_float4(acc[i][0], acc[i][1], acc[i][2], acc[i][3]);
            float4 o1 = make_float4(acc[i][4], acc[i][5], acc[i][6], acc[i][7]);
            *(float4*)&C[(size_t)r * 128 + tx * 8]     = o0;
            *(float4*)&C[(size_t)r * 128 + tx * 8 + 4] = o1;
        }
    }
}

// ---------------- edge scatter: agg[dst] += xw[src] * dinv[src]*dinv[dst] ----------------
__global__ void edge_kernel(const int* __restrict__ src, const int* __restrict__ dst,
                            const float* __restrict__ xw, float* __restrict__ agg, int E)
{
    int gw = (blockIdx.x * blockDim.x + threadIdx.x) >> 5;   // one warp per edge
    int lane = threadIdx.x & 31;
    if (gw >= E) return;
    int s = src[gw], d = dst[gw];
    float norm = g_dinv[s] * g_dinv[d];
    float4 v = *(const float4*)&xw[(size_t)s * 128 + lane * 4];
    v.x *= norm; v.y *= norm; v.z *= norm; v.w *= norm;
    red_add_v4(&agg[(size_t)d * 128 + lane * 4], v);
}

// ---------------- epilogue 1: h = relu(agg + xw*dinv^2 + b1) ----------------
__global__ void epi1_kernel(const float* __restrict__ agg, const float* __restrict__ xw,
                            const float* __restrict__ b1, float* __restrict__ h, int N)
{
    int i = blockIdx.x * blockDim.x + threadIdx.x;
    if (i >= N * 32) return;
    int row = i >> 5, c4 = i & 31;
    float di = g_dinv[row];
    float sl = di * di;
    float4 a = *(const float4*)&agg[(size_t)i * 4];
    float4 w = *(const float4*)&xw[(size_t)i * 4];
    float4 b = *(const float4*)&b1[c4 * 4];
    float4 o;
    o.x = fmaxf(fmaf(w.x, sl, a.x) + b.x, 0.f);
    o.y = fmaxf(fmaf(w.y, sl, a.y) + b.y, 0.f);
    o.z = fmaxf(fmaf(w.z, sl, a.z) + b.z, 0.f);
    o.w = fmaxf(fmaf(w.w, sl, a.w) + b.w, 0.f);
    *(float4*)&h[(size_t)i * 4] = o;
}

// ---------------- epilogue 2 + pool: sums[batch[row]] += agg + xw*dinv^2 + b2 ----------------
__global__ void epi2_pool_kernel(const float* __restrict__ agg, const float* __restrict__ xw,
                                 const float* __restrict__ b2, const int* __restrict__ batch, int N)
{
    int i = blockIdx.x * blockDim.x + threadIdx.x;
    if (i >= N * 32) return;
    int row = i >> 5, c4 = i & 31;
    float di = g_dinv[row];
    float sl = di * di;
    float4 a = *(const float4*)&agg[(size_t)i * 4];
    float4 w = *(const float4*)&xw[(size_t)i * 4];
    float4 b = *(const float4*)&b2[c4 * 4];
    float4 o;
    o.x = fmaf(w.x, sl, a.x) + b.x;
    o.y = fmaf(w.y, sl, a.y) + b.y;
    o.z = fmaf(w.z, sl, a.z) + b.z;
    o.w = fmaf(w.w, sl, a.w) + b.w;
    int gidx = batch[row];
    red_add_v4(&g_sums[(size_t)gidx * 128 + c4 * 4], o);
}

// ---------------- GRU step (h0=0) + relu + layernorm + linear head ----------------
__global__ __launch_bounds__(128) void gru_ln_out_kernel(
    const float* __restrict__ W_ih, const float* __restrict__ b_ih,
    const float* __restrict__ b_hh, const float* __restrict__ W_lin,
    const float* __restrict__ b_lin, float* __restrict__ out)
{
    int g = blockIdx.x;
    int tid = threadIdx.x;              // 128 threads
    int lane = tid & 31, w = tid >> 5;  // 4 warps

    __shared__ float gs[128];
    __shared__ float gi[384];
    __shared__ float rbuf1[4], rbuf2[4];

    float cnt = fmaxf(g_cnt[g], 1.0f);
    gs[tid] = g_sums[(size_t)g * 128 + tid] / cnt;
    __syncthreads();

    // gi[j] = <gs, W_ih[j,:]> + b_ih[j], j in [0,384). One warp per output row,
    // lanes stride K for coalesced W_ih reads.
    for (int j = w; j < 384; j += 4) {
        const float* wr = W_ih + (size_t)j * 128;
        float s = 0.f;
        #pragma unroll
        for (int t = 0; t < 4; t++) {
            int k = lane + t * 32;
            s += gs[k] * wr[k];
        }
        #pragma unroll
        for (int o = 16; o > 0; o >>= 1) s += __shfl_xor_sync(0xffffffffu, s, o);
        if (lane == 0) gi[j] = s + b_ih[j];
    }
    __syncthreads();

    // gates (PyTorch order r,z,n); h0 = 0 so gh = b_hh and output = (1-z)*n
    float r  = 1.f / (1.f + expf(-(gi[tid]       + b_hh[tid])));
    float z  = 1.f / (1.f + expf(-(gi[tid + 128] + b_hh[tid + 128])));
    float nn = tanhf(gi[tid + 256] + r * b_hh[tid + 256]);
    float v  = fmaxf((1.f - z) * nn, 0.f);   // relu

    // layernorm over 128
    float s1 = v, s2 = v * v;
    #pragma unroll
    for (int o = 16; o > 0; o >>= 1) {
        s1 += __shfl_xor_sync(0xffffffffu, s1, o);
        s2 += __shfl_xor_sync(0xffffffffu, s2, o);
    }
    if (lane == 0) { rbuf1[w] = s1; rbuf2[w] = s2; }
    __syncthreads();
    float S1 = rbuf1[0] + rbuf1[1] + rbuf1[2] + rbuf1[3];
    float S2 = rbuf2[0] + rbuf2[1] + rbuf2[2] + rbuf2[3];
    float mu  = S1 * (1.f / 128.f);
    float var = S2 * (1.f / 128.f) - mu * mu;
    float y = (v - mu) * rsqrtf(var + 1e-5f);

    // final linear head: out[g] = <y, W_lin> + b_lin
    float p = y * W_lin[tid];
    #pragma unroll
    for (int o = 16; o > 0; o >>= 1) p += __shfl_xor_sync(0xffffffffu, p, o);
    __syncthreads();                 // protect rbuf1 reuse
    if (lane == 0) rbuf1[w] = p;
    __syncthreads();
    if (tid == 0) out[g] = rbuf1[0] + rbuf1[1] + rbuf1[2] + rbuf1[3] + b_lin[0];
}

// ---------------- launch ----------------
extern "C" void kernel_launch(void* const* d_in, const int* in_sizes, int n_in,
                              void* d_out, int out_size)
{
    const float* x     = (const float*)d_in[0];
    const int*   ei    = (const int*)  d_in[1];
    const int*   batch = (const int*)  d_in[2];
    const float* W1    = (const float*)d_in[3];
    const float* b1    = (const float*)d_in[4];
    const float* W2    = (const float*)d_in[5];
    const float* b2    = (const float*)d_in[6];
    const float* W_ih  = (const float*)d_in[7];
    /* W_hh = d_in[8] unused: h0 == 0 */
    const float* b_ih  = (const float*)d_in[9];
    const float* b_hh  = (const float*)d_in[10];
    const float* W_lin = (const float*)d_in[11];
    const float* b_lin = (const float*)d_in[12];
    float* out = (float*)d_out;

    const int N = in_sizes[0] / 128;
    const int E = in_sizes[1] / 2;
    const int G = out_size;
    const int* srcp = ei;
    const int* dstp = ei + E;

    float *p_xw, *p_agg, *p_h;
    cudaGetSymbolAddress((void**)&p_xw,  g_xw);
    cudaGetSymbolAddress((void**)&p_agg, g_agg);
    cudaGetSymbolAddress((void**)&p_h,   g_h);

    const int T = 256;
    int n32  = N * 32;
    int bN32 = (n32 + T - 1) / T;
    int bN   = (N + T - 1) / T;
    int bE   = (E + T - 1) / T;
    long long ethreads = (long long)E * 32;
    int bEdge = (int)((ethreads + T - 1) / T);
    int bGemm = (N + 63) / 64;

    // prep
    zero_pre_kernel<<<bN32, T>>>(N, G);
    deg_kernel<<<bE, T>>>(dstp, E);
    cnt_kernel<<<bN, T>>>(batch, N);
    dinv_kernel<<<bN, T>>>(N);

    // conv1
    gemm_n128_kernel<<<bGemm, T>>>(x, W1, p_xw, N);
    edge_kernel<<<bEdge, T>>>(srcp, dstp, p_xw, p_agg, E);
    epi1_kernel<<<bN32, T>>>(p_agg, p_xw, b1, p_h, N);

    // conv2 + pool
    zero_agg_kernel<<<bN32, T>>>(N);
    gemm_n128_kernel<<<bGemm, T>>>(p_h, W2, p_xw, N);
    edge_kernel<<<bEdge, T>>>(srcp, dstp, p_xw, p_agg, E);
    epi2_pool_kernel<<<bN32, T>>>(p_agg, p_xw, b2, batch, N);

    // GRU + LN + head
    gru_ln_out_kernel<<<G, 128>>>(W_ih, b_ih, b_hh, W_lin, b_lin, out);
}

// round 3
// speedup vs baseline: 2.1392x; 2.1392x over previous
#include <cuda_runtime.h>
#include <math.h>
#include <stdint.h>

#define NODES_MAX 100000
#define EDGES_MAX 1600000
#define GRAPHS_MAX 2048

// ---------------- scratch (no allocations allowed) ----------------
__device__ float g_xw [NODES_MAX * 128];    // x @ W (per conv)
__device__ float g_h  [NODES_MAX * 128];    // hidden after conv1
__device__ float g_dinv[NODES_MAX];         // rsqrt(deg+1)
__device__ float g_sums[GRAPHS_MAX * 128];  // pooled sums
__device__ float g_cnt [GRAPHS_MAX];        // nodes per graph
__device__ float g_wt1_hi[128 * 128];       // W1^T tf32-hi  [n][k]
__device__ float g_wt1_lo[128 * 128];       // W1^T residual
__device__ float g_wt2_hi[128 * 128];
__device__ float g_wt2_lo[128 * 128];
// CSR build
__device__ int g_deg   [NODES_MAX];
__device__ int g_scan  [NODES_MAX];
__device__ int g_bsum  [1024];
__device__ int g_boff  [1024];
__device__ int g_rowptr[NODES_MAX + 1];
__device__ int g_cursor[NODES_MAX];
__device__ int g_es    [EDGES_MAX];         // src sorted by dst

// ---------------- helpers ----------------
__device__ __forceinline__ float tf32_rna(float x) {
    uint32_t u;
    asm("cvt.rna.tf32.f32 %0, %1;" : "=r"(u) : "f"(x));
    return __uint_as_float(u);
}
__device__ __forceinline__ void red_add_v4(float* addr, float4 v) {
    asm volatile("red.global.add.v4.f32 [%0], {%1,%2,%3,%4};"
                 :: "l"(addr), "f"(v.x), "f"(v.y), "f"(v.z), "f"(v.w) : "memory");
}
__device__ __forceinline__ void mma_tf32(float* c, const uint32_t* a, const uint32_t* b) {
    asm volatile(
        "mma.sync.aligned.m16n8k8.row.col.f32.tf32.tf32.f32 "
        "{%0,%1,%2,%3},{%4,%5,%6,%7},{%8,%9},{%0,%1,%2,%3};"
        : "+f"(c[0]), "+f"(c[1]), "+f"(c[2]), "+f"(c[3])
        : "r"(a[0]), "r"(a[1]), "r"(a[2]), "r"(a[3]), "r"(b[0]), "r"(b[1]));
}

// ---------------- prep ----------------
__global__ void zero_pre_kernel(int N, int G) {
    int i = blockIdx.x * blockDim.x + threadIdx.x;
    if (i < G * 32) *(float4*)&g_sums[(size_t)i * 4] = make_float4(0.f, 0.f, 0.f, 0.f);
    if (i < N) g_deg[i] = 0;
    if (i < G) g_cnt[i] = 0.f;
}
__global__ void deg_kernel(const int* __restrict__ dst, int E) {
    int i = blockIdx.x * blockDim.x + threadIdx.x;
    if (i < E) atomicAdd(&g_deg[dst[i]], 1);
}
__global__ void cnt_kernel(const int* __restrict__ batch, int N) {
    int i = blockIdx.x * blockDim.x + threadIdx.x;
    if (i < N) atomicAdd(&g_cnt[batch[i]], 1.0f);
}

// W^T + tf32 Dekker split for both conv weights
__global__ void wsplit_kernel(const float* __restrict__ W1, const float* __restrict__ W2) {
    int i = blockIdx.x * blockDim.x + threadIdx.x;
    if (i >= 128 * 128) return;
    int n = i >> 7, k = i & 127;
    float v1 = W1[k * 128 + n];
    float h1 = tf32_rna(v1);
    g_wt1_hi[i] = h1; g_wt1_lo[i] = tf32_rna(v1 - h1);
    float v2 = W2[k * 128 + n];
    float h2 = tf32_rna(v2);
    g_wt2_hi[i] = h2; g_wt2_lo[i] = tf32_rna(v2 - h2);
}

// ---------------- scan (deg -> rowptr/cursor/dinv) ----------------
__global__ void scan1_kernel(int N) {
    int i = blockIdx.x * 256 + threadIdx.x;
    int v = (i < N) ? g_deg[i] : 0;
    int lane = threadIdx.x & 31, w = threadIdx.x >> 5;
    int s = v;
    #pragma unroll
    for (int o = 1; o < 32; o <<= 1) {
        int t = __shfl_up_sync(0xffffffffu, s, o);
        if (lane >= o) s += t;
    }
    __shared__ int wsum[8];
    if (lane == 31) wsum[w] = s;
    __syncthreads();
    if (w == 0) {
        int ss = (lane < 8) ? wsum[lane] : 0;
        #pragma unroll
        for (int o = 1; o < 8; o <<= 1) {
            int u = __shfl_up_sync(0xffffffffu, ss, o);
            if (lane >= o) ss += u;
        }
        if (lane < 8) wsum[lane] = ss;
    }
    __syncthreads();
    s += (w > 0) ? wsum[w - 1] : 0;
    if (i < N) g_scan[i] = s;
    if (threadIdx.x == 255) g_bsum[blockIdx.x] = s;
}

__global__ void scan2_kernel(int nb) {
    int t = threadIdx.x;                     // 512 threads
    int v = (t < nb) ? g_bsum[t] : 0;
    int lane = t & 31, w = t >> 5;
    int s = v;
    #pragma unroll
    for (int o = 1; o < 32; o <<= 1) {
        int u = __shfl_up_sync(0xffffffffu, s, o);
        if (lane >= o) s += u;
    }
    __shared__ int wsum[16];
    if (lane == 31) wsum[w] = s;
    __syncthreads();
    if (w == 0) {
        int ss = (lane < 16) ? wsum[lane] : 0;
        #pragma unroll
        for (int o = 1; o < 16; o <<= 1) {
            int u = __shfl_up_sync(0xffffffffu, ss, o);
            if (lane >= o) ss += u;
        }
        if (lane < 16) wsum[lane] = ss;
    }
    __syncthreads();
    s += (w > 0) ? wsum[w - 1] : 0;
    if (t < nb) g_boff[t] = s;
}

__global__ void scan3_kernel(int N) {
    int i = blockIdx.x * blockDim.x + threadIdx.x;
    if (i >= N) return;
    int b = i >> 8;
    int incl = ((b > 0) ? g_boff[b - 1] : 0) + g_scan[i];
    g_rowptr[i + 1] = incl;
    g_cursor[i] = incl - g_deg[i];
    g_dinv[i] = rsqrtf((float)g_deg[i] + 1.0f);
    if (i == 0) g_rowptr[0] = 0;
}

__global__ void scatter_kernel(const int* __restrict__ src, const int* __restrict__ dst, int E) {
    int e = blockIdx.x * blockDim.x + threadIdx.x;
    if (e >= E) return;
    int d = dst[e];
    int pos = atomicAdd(&g_cursor[d], 1);
    g_es[pos] = src[e];
}

// ---------------- tensor GEMM: C[M,128] = A[M,128] @ Wt^T (3xTF32 split) ----------------
// smem: Whi[128][132] Wlo[128][132] Ahi[128][36] Alo[128][36]
static constexpr int SMO_WHI = 0;
static constexpr int SMO_WLO = 128 * 132 * 4;
static constexpr int SMO_AHI = 2 * 128 * 132 * 4;
static constexpr int SMO_ALO = 2 * 128 * 132 * 4 + 128 * 36 * 4;
static constexpr int SM_GEMM_TOTAL = 2 * 128 * 132 * 4 + 2 * 128 * 36 * 4;  // 172032

__global__ __launch_bounds__(256, 1) void gemm_tc_kernel(
    const float* __restrict__ A, const float* __restrict__ Wt_hi,
    const float* __restrict__ Wt_lo, float* __restrict__ C, int M)
{
    extern __shared__ char smem[];
    float* whi = (float*)(smem + SMO_WHI);
    float* wlo = (float*)(smem + SMO_WLO);
    float* ahi = (float*)(smem + SMO_AHI);
    float* alo = (float*)(smem + SMO_ALO);

    int tid = threadIdx.x, wid = tid >> 5, lane = tid & 31;
    int g = lane >> 2, tg = lane & 3;
    int row0 = blockIdx.x * 128;

    // load W tiles (once): 4096 float4 per split
    #pragma unroll
    for (int it = 0; it < 16; it++) {
        int idx = tid + it * 256;        // 0..4095
        int n = idx >> 5, c4 = idx & 31;
        float4 vh = *(const float4*)&Wt_hi[(size_t)n * 128 + c4 * 4];
        float4 vl = *(const float4*)&Wt_lo[(size_t)n * 128 + c4 * 4];
        *(float4*)&whi[n * 132 + c4 * 4] = vh;
        *(float4*)&wlo[n * 132 + c4 * 4] = vl;
    }

    float acc[16][4];
    #pragma unroll
    for (int nt = 0; nt < 16; nt++)
        #pragma unroll
        for (int j = 0; j < 4; j++) acc[nt][j] = 0.f;

    for (int kc = 0; kc < 128; kc += 32) {
        // load + split A chunk: 128 rows x 32 cols = 1024 float4
        #pragma unroll
        for (int it = 0; it < 4; it++) {
            int idx = tid + it * 256;    // 0..1023
            int r = idx >> 3, c4 = idx & 7;
            float4 v = make_float4(0.f, 0.f, 0.f, 0.f);
            if (row0 + r < M) v = *(const float4*)&A[(size_t)(row0 + r) * 128 + kc + c4 * 4];
            float4 hi, lo;
            hi.x = tf32_rna(v.x); lo.x = tf32_rna(v.x - hi.x);
            hi.y = tf32_rna(v.y); lo.y = tf32_rna(v.y - hi.y);
            hi.z = tf32_rna(v.z); lo.z = tf32_rna(v.z - hi.z);
            hi.w = tf32_rna(v.w); lo.w = tf32_rna(v.w - hi.w);
            *(float4*)&ahi[r * 36 + c4 * 4] = hi;
            *(float4*)&alo[r * 36 + c4 * 4] = lo;
        }
        __syncthreads();

        int arow = (wid * 16 + g) * 36;
        #pragma unroll
        for (int k0 = 0; k0 < 32; k0 += 8) {
            uint32_t ah[4], al[4];
            ah[0] = __float_as_uint(ahi[arow + k0 + tg]);
            ah[1] = __float_as_uint(ahi[arow + 8 * 36 + k0 + tg]);
            ah[2] = __float_as_uint(ahi[arow + k0 + tg + 4]);
            ah[3] = __float_as_uint(ahi[arow + 8 * 36 + k0 + tg + 4]);
            al[0] = __float_as_uint(alo[arow + k0 + tg]);
            al[1] = __float_as_uint(alo[arow + 8 * 36 + k0 + tg]);
            al[2] = __float_as_uint(alo[arow + k0 + tg + 4]);
            al[3] = __float_as_uint(alo[arow + 8 * 36 + k0 + tg + 4]);
            int kk = kc + k0;
            #pragma unroll
            for (int nt = 0; nt < 16; nt++) {
                int brow = (nt * 8 + g) * 132;
                uint32_t bh[2], bl[2];
                bh[0] = __float_as_uint(whi[brow + kk + tg]);
                bh[1] = __float_as_uint(whi[brow + kk + tg + 4]);
                bl[0] = __float_as_uint(wlo[brow + kk + tg]);
                bl[1] = __float_as_uint(wlo[brow + kk + tg + 4]);
                mma_tf32(acc[nt], ah, bh);
                mma_tf32(acc[nt], ah, bl);
                mma_tf32(acc[nt], al, bh);
            }
        }
        __syncthreads();
    }

    // epilogue
    int r0 = row0 + wid * 16 + g;
    int r1 = r0 + 8;
    #pragma unroll
    for (int nt = 0; nt < 16; nt++) {
        int col = nt * 8 + tg * 2;
        if (r0 < M) *(float2*)&C[(size_t)r0 * 128 + col] = make_float2(acc[nt][0], acc[nt][1]);
        if (r1 < M) *(float2*)&C[(size_t)r1 * 128 + col] = make_float2(acc[nt][2], acc[nt][3]);
    }
}

// ---------------- CSR aggregation (fused epilogue) ----------------
// acc = xw[d]*dinv[d]^2 + sum_{e in CSR(d)} xw[src]*dinv[src]*dinv[d] + bias
// POOL=false: h[d] = relu(acc).  POOL=true: sums[batch[d]] += acc.
template <bool POOL>
__global__ void agg_kernel(const float* __restrict__ xw, const float* __restrict__ bias,
                           float* __restrict__ hout, const int* __restrict__ batch, int N)
{
    int d = (blockIdx.x * blockDim.x + threadIdx.x) >> 5;
    int lane = threadIdx.x & 31;
    if (d >= N) return;

    float di = g_dinv[d];
    float sl = di * di;
    float4 acc = *(const float4*)&xw[(size_t)d * 128 + lane * 4];
    acc.x *= sl; acc.y *= sl; acc.z *= sl; acc.w *= sl;

    int e0 = g_rowptr[d], e1 = g_rowptr[d + 1];
    int e = e0;
    for (; e + 4 <= e1; e += 4) {
        int s0 = g_es[e], s1 = g_es[e + 1], s2 = g_es[e + 2], s3 = g_es[e + 3];
        float n0 = g_dinv[s0] * di, n1 = g_dinv[s1] * di;
        float n2 = g_dinv[s2] * di, n3 = g_dinv[s3] * di;
        float4 v0 = *(const float4*)&xw[(size_t)s0 * 128 + lane * 4];
        float4 v1 = *(const float4*)&xw[(size_t)s1 * 128 + lane * 4];
        float4 v2 = *(const float4*)&xw[(size_t)s2 * 128 + lane * 4];
        float4 v3 = *(const float4*)&xw[(size_t)s3 * 128 + lane * 4];
        acc.x = fmaf(v0.x, n0, fmaf(v1.x, n1, fmaf(v2.x, n2, fmaf(v3.x, n3, acc.x))));
        acc.y = fmaf(v0.y, n0, fmaf(v1.y, n1, fmaf(v2.y, n2, fmaf(v3.y, n3, acc.y))));
        acc.z = fmaf(v0.z, n0, fmaf(v1.z, n1, fmaf(v2.z, n2, fmaf(v3.z, n3, acc.z))));
        acc.w = fmaf(v0.w, n0, fmaf(v1.w, n1, fmaf(v2.w, n2, fmaf(v3.w, n3, acc.w))));
    }
    for (; e < e1; e++) {
        int s = g_es[e];
        float nm = g_dinv[s] * di;
        float4 v = *(const float4*)&xw[(size_t)s * 128 + lane * 4];
        acc.x = fmaf(v.x, nm, acc.x);
        acc.y = fmaf(v.y, nm, acc.y);
        acc.z = fmaf(v.z, nm, acc.z);
        acc.w = fmaf(v.w, nm, acc.w);
    }

    float4 b = *(const float4*)&bias[lane * 4];
    acc.x += b.x; acc.y += b.y; acc.z += b.z; acc.w += b.w;

    if (POOL) {
        int gi = batch[d];
        red_add_v4(&g_sums[(size_t)gi * 128 + lane * 4], acc);
    } else {
        acc.x = fmaxf(acc.x, 0.f); acc.y = fmaxf(acc.y, 0.f);
        acc.z = fmaxf(acc.z, 0.f); acc.w = fmaxf(acc.w, 0.f);
        *(float4*)&hout[(size_t)d * 128 + lane * 4] = acc;
    }
}

// ---------------- GRU step (h0=0) + relu + layernorm + linear head ----------------
__global__ __launch_bounds__(128) void gru_ln_out_kernel(
    const float* __restrict__ W_ih, const float* __restrict__ b_ih,
    const float* __restrict__ b_hh, const float* __restrict__ W_lin,
    const float* __restrict__ b_lin, float* __restrict__ out)
{
    int g = blockIdx.x;
    int tid = threadIdx.x;
    int lane = tid & 31, w = tid >> 5;

    __shared__ float gs[128];
    __shared__ float gi[384];
    __shared__ float rbuf1[4], rbuf2[4];

    float cnt = fmaxf(g_cnt[g], 1.0f);
    gs[tid] = g_sums[(size_t)g * 128 + tid] / cnt;
    __syncthreads();

    for (int j = w; j < 384; j += 4) {
        const float* wr = W_ih + (size_t)j * 128;
        float s = 0.f;
        #pragma unroll
        for (int t = 0; t < 4; t++) {
            int k = lane + t * 32;
            s += gs[k] * wr[k];
        }
        #pragma unroll
        for (int o = 16; o > 0; o >>= 1) s += __shfl_xor_sync(0xffffffffu, s, o);
        if (lane == 0) gi[j] = s + b_ih[j];
    }
    __syncthreads();

    float r  = 1.f / (1.f + expf(-(gi[tid]       + b_hh[tid])));
    float z  = 1.f / (1.f + expf(-(gi[tid + 128] + b_hh[tid + 128])));
    float nn = tanhf(gi[tid + 256] + r * b_hh[tid + 256]);
    float v  = fmaxf((1.f - z) * nn, 0.f);

    float s1 = v, s2 = v * v;
    #pragma unroll
    for (int o = 16; o > 0; o >>= 1) {
        s1 += __shfl_xor_sync(0xffffffffu, s1, o);
        s2 += __shfl_xor_sync(0xffffffffu, s2, o);
    }
    if (lane == 0) { rbuf1[w] = s1; rbuf2[w] = s2; }
    __syncthreads();
    float S1 = rbuf1[0] + rbuf1[1] + rbuf1[2] + rbuf1[3];
    float S2 = rbuf2[0] + rbuf2[1] + rbuf2[2] + rbuf2[3];
    float mu  = S1 * (1.f / 128.f);
    float var = S2 * (1.f / 128.f) - mu * mu;
    float y = (v - mu) * rsqrtf(var + 1e-5f);

    float p = y * W_lin[tid];
    #pragma unroll
    for (int o = 16; o > 0; o >>= 1) p += __shfl_xor_sync(0xffffffffu, p, o);
    __syncthreads();
    if (lane == 0) rbuf1[w] = p;
    __syncthreads();
    if (tid == 0) out[g] = rbuf1[0] + rbuf1[1] + rbuf1[2] + rbuf1[3] + b_lin[0];
}

// ---------------- launch ----------------
extern "C" void kernel_launch(void* const* d_in, const int* in_sizes, int n_in,
                              void* d_out, int out_size)
{
    const float* x     = (const float*)d_in[0];
    const int*   ei    = (const int*)  d_in[1];
    const int*   batch = (const int*)  d_in[2];
    const float* W1    = (const float*)d_in[3];
    const float* b1    = (const float*)d_in[4];
    const float* W2    = (const float*)d_in[5];
    const float* b2    = (const float*)d_in[6];
    const float* W_ih  = (const float*)d_in[7];
    /* W_hh = d_in[8] unused: h0 == 0 */
    const float* b_ih  = (const float*)d_in[9];
    const float* b_hh  = (const float*)d_in[10];
    const float* W_lin = (const float*)d_in[11];
    const float* b_lin = (const float*)d_in[12];
    float* out = (float*)d_out;

    const int N = in_sizes[0] / 128;
    const int E = in_sizes[1] / 2;
    const int G = out_size;
    const int* srcp = ei;
    const int* dstp = ei + E;

    float *p_xw, *p_h, *p_w1h, *p_w1l, *p_w2h, *p_w2l;
    cudaGetSymbolAddress((void**)&p_xw,  g_xw);
    cudaGetSymbolAddress((void**)&p_h,   g_h);
    cudaGetSymbolAddress((void**)&p_w1h, g_wt1_hi);
    cudaGetSymbolAddress((void**)&p_w1l, g_wt1_lo);
    cudaGetSymbolAddress((void**)&p_w2h, g_wt2_hi);
    cudaGetSymbolAddress((void**)&p_w2l, g_wt2_lo);

    static bool attr_set = false;
    if (!attr_set) {
        cudaFuncSetAttribute(gemm_tc_kernel,
                             cudaFuncAttributeMaxDynamicSharedMemorySize, SM_GEMM_TOTAL);
        attr_set = true;
    }

    const int T = 256;
    int bN   = (N + T - 1) / T;
    int bE   = (E + T - 1) / T;
    int nz   = (N > G * 32) ? N : G * 32;
    int bZ   = (nz + T - 1) / T;
    int nb   = (N + 255) / 256;                   // scan blocks
    long long wthreads = (long long)N * 32;
    int bAgg = (int)((wthreads + T - 1) / T);
    int bGemm = (N + 127) / 128;

    // prep + CSR build
    zero_pre_kernel<<<bZ, T>>>(N, G);
    deg_kernel<<<bE, T>>>(dstp, E);
    cnt_kernel<<<bN, T>>>(batch, N);
    wsplit_kernel<<<(128 * 128 + T - 1) / T, T>>>(W1, W2);
    scan1_kernel<<<nb, 256>>>(N);
    scan2_kernel<<<1, 512>>>(nb);
    scan3_kernel<<<bN, T>>>(N);
    scatter_kernel<<<bE, T>>>(srcp, dstp, E);

    // conv1: xw = x@W1 ; h = relu(agg + self + b1)
    gemm_tc_kernel<<<bGemm, 256, SM_GEMM_TOTAL>>>(x, p_w1h, p_w1l, p_xw, N);
    agg_kernel<false><<<bAgg, T>>>(p_xw, b1, p_h, batch, N);

    // conv2 + pool: xw = h@W2 ; sums[batch] += agg + self + b2
    gemm_tc_kernel<<<bGemm, 256, SM_GEMM_TOTAL>>>(p_h, p_w2h, p_w2l, p_xw, N);
    agg_kernel<true><<<bAgg, T>>>(p_xw, b2, nullptr, batch, N);

    // GRU + LN + head
    gru_ln_out_kernel<<<G, 128>>>(W_ih, b_ih, b_hh, W_lin, b_lin, out);
}

// round 4
// speedup vs baseline: 2.4246x; 1.1334x over previous
#include <cuda_runtime.h>
#include <math.h>
#include <stdint.h>

#define NODES_MAX 100000
#define EDGES_MAX 1600000
#define GRAPHS_MAX 2048

// ---------------- scratch (no allocations allowed) ----------------
__device__ float g_xw [NODES_MAX * 128];    // x @ W (per conv)
__device__ float g_h  [NODES_MAX * 128];    // hidden after conv1
__device__ float g_dinv[NODES_MAX];         // rsqrt(deg+1)
__device__ float g_sums[GRAPHS_MAX * 128];  // pooled sums
__device__ float g_cnt [GRAPHS_MAX];        // nodes per graph
__device__ float4 g_wbuf1[8192];            // W1 in mma-fragment order (hi,hi,lo,lo)
__device__ float4 g_wbuf2[8192];            // W2 likewise
// CSR build
__device__ int g_deg   [NODES_MAX];
__device__ int g_scan  [NODES_MAX];
__device__ int g_bsum  [1024];
__device__ int g_boff  [1024];
__device__ int g_rowptr[NODES_MAX + 1];
__device__ int g_cursor[NODES_MAX];
__device__ int g_es    [EDGES_MAX];         // src sorted by dst

// ---------------- helpers ----------------
__device__ __forceinline__ float tf32_rna(float x) {
    uint32_t u;
    asm("cvt.rna.tf32.f32 %0, %1;" : "=r"(u) : "f"(x));
    return __uint_as_float(u);
}
__device__ __forceinline__ void red_add_v4(float* addr, float4 v) {
    asm volatile("red.global.add.v4.f32 [%0], {%1,%2,%3,%4};"
                 :: "l"(addr), "f"(v.x), "f"(v.y), "f"(v.z), "f"(v.w) : "memory");
}
__device__ __forceinline__ void mma_tf32(float* c, const uint32_t* a, const uint32_t* b) {
    asm volatile(
        "mma.sync.aligned.m16n8k8.row.col.f32.tf32.tf32.f32 "
        "{%0,%1,%2,%3},{%4,%5,%6,%7},{%8,%9},{%0,%1,%2,%3};"
        : "+f"(c[0]), "+f"(c[1]), "+f"(c[2]), "+f"(c[3])
        : "r"(a[0]), "r"(a[1]), "r"(a[2]), "r"(a[3]), "r"(b[0]), "r"(b[1]));
}
__device__ __forceinline__ uint32_t smem_u32(const void* p) {
    uint32_t a;
    asm("{ .reg .u64 t; cvta.to.shared.u64 t, %1; cvt.u32.u64 %0, t; }" : "=r"(a) : "l"(p));
    return a;
}
__device__ __forceinline__ void cp_async16(uint32_t dst, const void* src, bool pred) {
    int sz = pred ? 16 : 0;
    asm volatile("cp.async.cg.shared.global [%0], [%1], 16, %2;"
                 :: "r"(dst), "l"(src), "r"(sz) : "memory");
}
__device__ __forceinline__ void cp_commit() {
    asm volatile("cp.async.commit_group;" ::: "memory");
}
template <int NW>
__device__ __forceinline__ void cp_wait_group() {
    asm volatile("cp.async.wait_group %0;" :: "n"(NW) : "memory");
}

// ---------------- prep ----------------
__global__ void zero_pre_kernel(int N, int G) {
    int i = blockIdx.x * blockDim.x + threadIdx.x;
    if (i < G * 32) *(float4*)&g_sums[(size_t)i * 4] = make_float4(0.f, 0.f, 0.f, 0.f);
    if (i < N) g_deg[i] = 0;
    if (i < G) g_cnt[i] = 0.f;
}
__global__ void degcnt_kernel(const int* __restrict__ dst, const int* __restrict__ batch,
                              int E, int N) {
    int i = blockIdx.x * blockDim.x + threadIdx.x;
    if (i < E) atomicAdd(&g_deg[dst[i]], 1);
    if (i < N) atomicAdd(&g_cnt[batch[i]], 1.0f);
}

// W -> mma-fragment-order interleaved tf32 split buffers.
// wbuf[((kk*16)+nt)*32 + lane] = {Whi[n][klo], Whi[n][khi], Wlo[n][klo], Wlo[n][khi]}
// with n = nt*8 + (lane>>2), klo = kk*8 + (lane&3), khi = klo+4, kk = kc*4+k0.
__global__ void wsplit_kernel(const float* __restrict__ W1, const float* __restrict__ W2) {
    int i = blockIdx.x * blockDim.x + threadIdx.x;
    if (i >= 2 * 8192) return;
    int conv = i >> 13;
    int idx = i & 8191;
    int lane = idx & 31, nt = (idx >> 5) & 15, kk = idx >> 9;
    int g = lane >> 2, tg = lane & 3;
    int n = nt * 8 + g;
    int klo = kk * 8 + tg, khi = klo + 4;
    const float* W = conv ? W2 : W1;
    float v0 = W[klo * 128 + n];
    float v1 = W[khi * 128 + n];
    float h0 = tf32_rna(v0), h1 = tf32_rna(v1);
    float4 o = make_float4(h0, h1, v0 - h0, v1 - h1);   // residuals: hw-truncated in mma, err <= 2^-24
    if (conv) g_wbuf2[idx] = o; else g_wbuf1[idx] = o;
}

// ---------------- scan (deg -> rowptr/cursor/dinv) ----------------
__global__ void scan1_kernel(int N) {
    int i = blockIdx.x * 256 + threadIdx.x;
    int v = (i < N) ? g_deg[i] : 0;
    int lane = threadIdx.x & 31, w = threadIdx.x >> 5;
    int s = v;
    #pragma unroll
    for (int o = 1; o < 32; o <<= 1) {
        int t = __shfl_up_sync(0xffffffffu, s, o);
        if (lane >= o) s += t;
    }
    __shared__ int wsum[8];
    if (lane == 31) wsum[w] = s;
    __syncthreads();
    if (w == 0) {
        int ss = (lane < 8) ? wsum[lane] : 0;
        #pragma unroll
        for (int o = 1; o < 8; o <<= 1) {
            int u = __shfl_up_sync(0xffffffffu, ss, o);
            if (lane >= o) ss += u;
        }
        if (lane < 8) wsum[lane] = ss;
    }
    __syncthreads();
    s += (w > 0) ? wsum[w - 1] : 0;
    if (i < N) g_scan[i] = s;
    if (threadIdx.x == 255) g_bsum[blockIdx.x] = s;
}

__global__ void scan2_kernel(int nb) {
    int t = threadIdx.x;                     // 512 threads
    int v = (t < nb) ? g_bsum[t] : 0;
    int lane = t & 31, w = t >> 5;
    int s = v;
    #pragma unroll
    for (int o = 1; o < 32; o <<= 1) {
        int u = __shfl_up_sync(0xffffffffu, s, o);
        if (lane >= o) s += u;
    }
    __shared__ int wsum[16];
    if (lane == 31) wsum[w] = s;
    __syncthreads();
    if (w == 0) {
        int ss = (lane < 16) ? wsum[lane] : 0;
        #pragma unroll
        for (int o = 1; o < 16; o <<= 1) {
            int u = __shfl_up_sync(0xffffffffu, ss, o);
            if (lane >= o) ss += u;
        }
        if (lane < 16) wsum[lane] = ss;
    }
    __syncthreads();
    s += (w > 0) ? wsum[w - 1] : 0;
    if (t < nb) g_boff[t] = s;
}

__global__ void scan3_kernel(int N) {
    int i = blockIdx.x * blockDim.x + threadIdx.x;
    if (i >= N) return;
    int b = i >> 8;
    int incl = ((b > 0) ? g_boff[b - 1] : 0) + g_scan[i];
    g_rowptr[i + 1] = incl;
    g_cursor[i] = incl - g_deg[i];
    g_dinv[i] = rsqrtf((float)g_deg[i] + 1.0f);
    if (i == 0) g_rowptr[0] = 0;
}

__global__ void scatter_kernel(const int* __restrict__ src, const int* __restrict__ dst, int E) {
    int e = blockIdx.x * blockDim.x + threadIdx.x;
    if (e >= E) return;
    int d = dst[e];
    int pos = atomicAdd(&g_cursor[d], 1);
    g_es[pos] = src[e];
}

// ---------------- tensor GEMM: C[M,128] = A[M,128] @ W (3xTF32, fragment-order W) ----------
// smem: Ws = 8192 float4 (128KB, fragment-interleaved), As = 128 rows x stride 144 fp32 raw.
static constexpr int SM_WS_BYTES = 8192 * 16;          // 131072
static constexpr int AS_STRIDE   = 144;                // floats; banks: (4r+k)%32 -> conflict-free
static constexpr int SM_GEMM_TOTAL = SM_WS_BYTES + 128 * AS_STRIDE * 4;  // 204800

__global__ __launch_bounds__(256, 1) void gemm_tc_kernel(
    const float* __restrict__ A, const float4* __restrict__ Wbuf,
    float* __restrict__ C, int M)
{
    extern __shared__ char smem[];
    float4* Ws = (float4*)smem;
    float*  As = (float*)(smem + SM_WS_BYTES);
    uint32_t ws_b = smem_u32(Ws), as_b = smem_u32(As);

    int tid = threadIdx.x, wid = tid >> 5, lane = tid & 31;
    int g = lane >> 2, tg = lane & 3;
    int wm = wid & 1, wn = wid >> 1;         // warp tile: m64 x n32
    int row0 = blockIdx.x * 128;

    // W: 8192 float4, 32 per thread (group 0 together with A chunk 0)
    #pragma unroll
    for (int it = 0; it < 32; it++) {
        int idx = it * 256 + tid;
        cp_async16(ws_b + idx * 16, Wbuf + idx, true);
    }
    // A chunks: per kc, 1024 float4 (128 rows x 8 float4)
    #pragma unroll
    for (int kc = 0; kc < 4; kc++) {
        #pragma unroll
        for (int it = 0; it < 4; it++) {
            int j = it * 256 + tid;          // 0..1023
            int r = j >> 3, c4 = j & 7;
            int col = kc * 32 + c4 * 4;
            bool pred = (row0 + r) < M;
            int r_eff = pred ? (row0 + r) : 0;
            cp_async16(as_b + (r * AS_STRIDE + col) * 4, A + (size_t)r_eff * 128 + col, pred);
        }
        cp_commit();                          // groups: G0=W+A0, G1=A1, G2=A2, G3=A3
    }

    float acc[4][4][4];
    #pragma unroll
    for (int mi = 0; mi < 4; mi++)
        #pragma unroll
        for (int ni = 0; ni < 4; ni++)
            #pragma unroll
            for (int j = 0; j < 4; j++) acc[mi][ni][j] = 0.f;

    #pragma unroll
    for (int kc = 0; kc < 4; kc++) {
        if      (kc == 0) cp_wait_group<3>();
        else if (kc == 1) cp_wait_group<2>();
        else if (kc == 2) cp_wait_group<1>();
        else              cp_wait_group<0>();
        __syncthreads();

        #pragma unroll
        for (int k0 = 0; k0 < 4; k0++) {
            int kb = kc * 32 + k0 * 8;
            // A fragments (split to tf32 hi + raw residual at load time)
            uint32_t ah[4][4], al[4][4];
            #pragma unroll
            for (int mi = 0; mi < 4; mi++) {
                int r = wm * 64 + mi * 16 + g;
                float v0 = As[r * AS_STRIDE + kb + tg];
                float v1 = As[(r + 8) * AS_STRIDE + kb + tg];
                float v2 = As[r * AS_STRIDE + kb + tg + 4];
                float v3 = As[(r + 8) * AS_STRIDE + kb + tg + 4];
                float h;
                h = tf32_rna(v0); ah[mi][0] = __float_as_uint(h); al[mi][0] = __float_as_uint(v0 - h);
                h = tf32_rna(v1); ah[mi][1] = __float_as_uint(h); al[mi][1] = __float_as_uint(v1 - h);
                h = tf32_rna(v2); ah[mi][2] = __float_as_uint(h); al[mi][2] = __float_as_uint(v2 - h);
                h = tf32_rna(v3); ah[mi][3] = __float_as_uint(h); al[mi][3] = __float_as_uint(v3 - h);
            }
            // B fragments: one LDS.128 each, then 3-term mma
            #pragma unroll
            for (int ni = 0; ni < 4; ni++) {
                int nt = wn * 4 + ni;
                float4 w4 = Ws[(kc * 4 + k0) * 512 + nt * 32 + lane];
                uint32_t bh[2] = { __float_as_uint(w4.x), __float_as_uint(w4.y) };
                uint32_t bl[2] = { __float_as_uint(w4.z), __float_as_uint(w4.w) };
                #pragma unroll
                for (int mi = 0; mi < 4; mi++) {
                    mma_tf32(acc[mi][ni], ah[mi], bh);
                    mma_tf32(acc[mi][ni], ah[mi], bl);
                    mma_tf32(acc[mi][ni], al[mi], bh);
                }
            }
        }
    }

    // epilogue
    #pragma unroll
    for (int mi = 0; mi < 4; mi++) {
        int r0 = row0 + wm * 64 + mi * 16 + g;
        int r1 = r0 + 8;
        #pragma unroll
        for (int ni = 0; ni < 4; ni++) {
            int col = wn * 32 + ni * 8 + tg * 2;
            if (r0 < M) *(float2*)&C[(size_t)r0 * 128 + col] = make_float2(acc[mi][ni][0], acc[mi][ni][1]);
            if (r1 < M) *(float2*)&C[(size_t)r1 * 128 + col] = make_float2(acc[mi][ni][2], acc[mi][ni][3]);
        }
    }
}

// ---------------- CSR aggregation (fused epilogue) ----------------
template <bool POOL>
__global__ void agg_kernel(const float* __restrict__ xw, const float* __restrict__ bias,
                           float* __restrict__ hout, const int* __restrict__ batch, int N)
{
    int d = (blockIdx.x * blockDim.x + threadIdx.x) >> 5;
    int lane = threadIdx.x & 31;
    if (d >= N) return;

    float di = g_dinv[d];
    float sl = di * di;
    float4 acc = *(const float4*)&xw[(size_t)d * 128 + lane * 4];
    acc.x *= sl; acc.y *= sl; acc.z *= sl; acc.w *= sl;

    int e0 = g_rowptr[d], e1 = g_rowptr[d + 1];
    int e = e0;
    for (; e + 4 <= e1; e += 4) {
        int s0 = g_es[e], s1 = g_es[e + 1], s2 = g_es[e + 2], s3 = g_es[e + 3];
        float n0 = g_dinv[s0] * di, n1 = g_dinv[s1] * di;
        float n2 = g_dinv[s2] * di, n3 = g_dinv[s3] * di;
        float4 v0 = *(const float4*)&xw[(size_t)s0 * 128 + lane * 4];
        float4 v1 = *(const float4*)&xw[(size_t)s1 * 128 + lane * 4];
        float4 v2 = *(const float4*)&xw[(size_t)s2 * 128 + lane * 4];
        float4 v3 = *(const float4*)&xw[(size_t)s3 * 128 + lane * 4];
        acc.x = fmaf(v0.x, n0, fmaf(v1.x, n1, fmaf(v2.x, n2, fmaf(v3.x, n3, acc.x))));
        acc.y = fmaf(v0.y, n0, fmaf(v1.y, n1, fmaf(v2.y, n2, fmaf(v3.y, n3, acc.y))));
        acc.z = fmaf(v0.z, n0, fmaf(v1.z, n1, fmaf(v2.z, n2, fmaf(v3.z, n3, acc.z))));
        acc.w = fmaf(v0.w, n0, fmaf(v1.w, n1, fmaf(v2.w, n2, fmaf(v3.w, n3, acc.w))));
    }
    for (; e < e1; e++) {
        int s = g_es[e];
        float nm = g_dinv[s] * di;
        float4 v = *(const float4*)&xw[(size_t)s * 128 + lane * 4];
        acc.x = fmaf(v.x, nm, acc.x);
        acc.y = fmaf(v.y, nm, acc.y);
        acc.z = fmaf(v.z, nm, acc.z);
        acc.w = fmaf(v.w, nm, acc.w);
    }

    float4 b = *(const float4*)&bias[lane * 4];
    acc.x += b.x; acc.y += b.y; acc.z += b.z; acc.w += b.w;

    if (POOL) {
        int gi = batch[d];
        red_add_v4(&g_sums[(size_t)gi * 128 + lane * 4], acc);
    } else {
        acc.x = fmaxf(acc.x, 0.f); acc.y = fmaxf(acc.y, 0.f);
        acc.z = fmaxf(acc.z, 0.f); acc.w = fmaxf(acc.w, 0.f);
        *(float4*)&hout[(size_t)d * 128 + lane * 4] = acc;
    }
}

// ---------------- GRU step (h0=0) + relu + layernorm + linear head ----------------
__global__ __launch_bounds__(128) void gru_ln_out_kernel(
    const float* __restrict__ W_ih, const float* __restrict__ b_ih,
    const float* __restrict__ b_hh, const float* __restrict__ W_lin,
    const float* __restrict__ b_lin, float* __restrict__ out)
{
    int g = blockIdx.x;
    int tid = threadIdx.x;
    int lane = tid & 31, w = tid >> 5;

    __shared__ float gs[128];
    __shared__ float gi[384];
    __shared__ float rbuf1[4], rbuf2[4];

    float cnt = fmaxf(g_cnt[g], 1.0f);
    gs[tid] = g_sums[(size_t)g * 128 + tid] / cnt;
    __syncthreads();

    for (int j = w; j < 384; j += 4) {
        const float* wr = W_ih + (size_t)j * 128;
        float s = 0.f;
        #pragma unroll
        for (int t = 0; t < 4; t++) {
            int k = lane + t * 32;
            s += gs[k] * wr[k];
        }
        #pragma unroll
        for (int o = 16; o > 0; o >>= 1) s += __shfl_xor_sync(0xffffffffu, s, o);
        if (lane == 0) gi[j] = s + b_ih[j];
    }
    __syncthreads();

    float r  = 1.f / (1.f + expf(-(gi[tid]       + b_hh[tid])));
    float z  = 1.f / (1.f + expf(-(gi[tid + 128] + b_hh[tid + 128])));
    float nn = tanhf(gi[tid + 256] + r * b_hh[tid + 256]);
    float v  = fmaxf((1.f - z) * nn, 0.f);

    float s1 = v, s2 = v * v;
    #pragma unroll
    for (int o = 16; o > 0; o >>= 1) {
        s1 += __shfl_xor_sync(0xffffffffu, s1, o);
        s2 += __shfl_xor_sync(0xffffffffu, s2, o);
    }
    if (lane == 0) { rbuf1[w] = s1; rbuf2[w] = s2; }
    __syncthreads();
    float S1 = rbuf1[0] + rbuf1[1] + rbuf1[2] + rbuf1[3];
    float S2 = rbuf2[0] + rbuf2[1] + rbuf2[2] + rbuf2[3];
    float mu  = S1 * (1.f / 128.f);
    float var = S2 * (1.f / 128.f) - mu * mu;
    float y = (v - mu) * rsqrtf(var + 1e-5f);

    float p = y * W_lin[tid];
    #pragma unroll
    for (int o = 16; o > 0; o >>= 1) p += __shfl_xor_sync(0xffffffffu, p, o);
    __syncthreads();
    if (lane == 0) rbuf1[w] = p;
    __syncthreads();
    if (tid == 0) out[g] = rbuf1[0] + rbuf1[1] + rbuf1[2] + rbuf1[3] + b_lin[0];
}

// ---------------- launch ----------------
extern "C" void kernel_launch(void* const* d_in, const int* in_sizes, int n_in,
                              void* d_out, int out_size)
{
    const float* x     = (const float*)d_in[0];
    const int*   ei    = (const int*)  d_in[1];
    const int*   batch = (const int*)  d_in[2];
    const float* W1    = (const float*)d_in[3];
    const float* b1    = (const float*)d_in[4];
    const float* W2    = (const float*)d_in[5];
    const float* b2    = (const float*)d_in[6];
    const float* W_ih  = (const float*)d_in[7];
    /* W_hh = d_in[8] unused: h0 == 0 */
    const float* b_ih  = (const float*)d_in[9];
    const float* b_hh  = (const float*)d_in[10];
    const float* W_lin = (const float*)d_in[11];
    const float* b_lin = (const float*)d_in[12];
    float* out = (float*)d_out;

    const int N = in_sizes[0] / 128;
    const int E = in_sizes[1] / 2;
    const int G = out_size;
    const int* srcp = ei;
    const int* dstp = ei + E;

    float *p_xw, *p_h;
    float4 *p_wb1, *p_wb2;
    cudaGetSymbolAddress((void**)&p_xw,  g_xw);
    cudaGetSymbolAddress((void**)&p_h,   g_h);
    cudaGetSymbolAddress((void**)&p_wb1, g_wbuf1);
    cudaGetSymbolAddress((void**)&p_wb2, g_wbuf2);

    static cudaStream_t s_side = nullptr;
    static cudaEvent_t ev_fork = nullptr, ev_join = nullptr;
    if (!s_side) {
        cudaFuncSetAttribute(gemm_tc_kernel,
                             cudaFuncAttributeMaxDynamicSharedMemorySize, SM_GEMM_TOTAL);
        cudaStreamCreateWithFlags(&s_side, cudaStreamNonBlocking);
        cudaEventCreateWithFlags(&ev_fork, cudaEventDisableTiming);
        cudaEventCreateWithFlags(&ev_join, cudaEventDisableTiming);
    }

    const int T = 256;
    int bN   = (N + T - 1) / T;
    int bE   = (E + T - 1) / T;
    int nz   = (N > G * 32) ? N : G * 32;
    int bZ   = (nz + T - 1) / T;
    int nb   = (N + 255) / 256;
    long long wthreads = (long long)N * 32;
    int bAgg = (int)((wthreads + T - 1) / T);
    int bGemm = (N + 127) / 128;

    // fork: CSR build on side stream, GEMM path on main stream
    cudaEventRecord(ev_fork, 0);
    cudaStreamWaitEvent(s_side, ev_fork, 0);

    zero_pre_kernel<<<bZ, T, 0, s_side>>>(N, G);
    degcnt_kernel<<<bE, T, 0, s_side>>>(dstp, batch, E, N);
    scan1_kernel<<<nb, 256, 0, s_side>>>(N);
    scan2_kernel<<<1, 512, 0, s_side>>>(nb);
    scan3_kernel<<<bN, T, 0, s_side>>>(N);
    scatter_kernel<<<bE, T, 0, s_side>>>(srcp, dstp, E);
    cudaEventRecord(ev_join, s_side);

    // main stream: weight split + GEMM1 overlap the CSR build
    wsplit_kernel<<<(2 * 8192 + T - 1) / T, T>>>(W1, W2);
    gemm_tc_kernel<<<bGemm, 256, SM_GEMM_TOTAL>>>(x, p_wb1, p_xw, N);

    cudaStreamWaitEvent(0, ev_join, 0);

    // conv1 aggregate, conv2, pool
    agg_kernel<false><<<bAgg, T>>>(p_xw, b1, p_h, batch, N);
    gemm_tc_kernel<<<bGemm, 256, SM_GEMM_TOTAL>>>(p_h, p_wb2, p_xw, N);
    agg_kernel<true><<<bAgg, T>>>(p_xw, b2, nullptr, batch, N);

    // GRU + LN + head
    gru_ln_out_kernel<<<G, 128>>>(W_ih, b_ih, b_hh, W_lin, b_lin, out);
}

// round 5
// speedup vs baseline: 2.7422x; 1.1310x over previous
#include <cuda_runtime.h>
#include <cuda_bf16.h>
#include <math.h>
#include <stdint.h>

#define NODES_MAX 100000
#define EDGES_MAX 1600000
#define GRAPHS_MAX 2048

// ---------------- scratch (no allocations allowed) ----------------
__device__ float g_xw [NODES_MAX * 128];    // x @ W (per conv)
__device__ float g_h  [NODES_MAX * 128];    // hidden after conv1
__device__ float g_dinv[NODES_MAX];         // rsqrt(deg+1)
__device__ float g_sums[GRAPHS_MAX * 128];  // pooled sums
__device__ float g_cnt [GRAPHS_MAX];        // nodes per graph
__device__ uint4 g_wbuf1[4096];             // W1 bf16 fragment order {bh0,bh1,bl0,bl1}
__device__ uint4 g_wbuf2[4096];             // W2 likewise
// CSR build
__device__ int   g_deg   [NODES_MAX];
__device__ int   g_scan  [NODES_MAX];
__device__ int   g_bsum  [1024];
__device__ int   g_boff  [1024];
__device__ int   g_rowptr[NODES_MAX + 1];
__device__ int   g_cursor[NODES_MAX];
__device__ int   g_es    [EDGES_MAX];       // src sorted by dst
__device__ float g_enorm [EDGES_MAX];       // dinv[src]*dinv[dst] per CSR slot

// ---------------- helpers ----------------
__device__ __forceinline__ void red_add_v4(float* addr, float4 v) {
    asm volatile("red.global.add.v4.f32 [%0], {%1,%2,%3,%4};"
                 :: "l"(addr), "f"(v.x), "f"(v.y), "f"(v.z), "f"(v.w) : "memory");
}
__device__ __forceinline__ void mma_bf16(float* c, const uint32_t* a, const uint32_t* b) {
    asm volatile(
        "mma.sync.aligned.m16n8k16.row.col.f32.bf16.bf16.f32 "
        "{%0,%1,%2,%3},{%4,%5,%6,%7},{%8,%9},{%0,%1,%2,%3};"
        : "+f"(c[0]), "+f"(c[1]), "+f"(c[2]), "+f"(c[3])
        : "r"(a[0]), "r"(a[1]), "r"(a[2]), "r"(a[3]), "r"(b[0]), "r"(b[1]));
}
__device__ __forceinline__ uint32_t smem_u32(const void* p) {
    uint32_t a;
    asm("{ .reg .u64 t; cvta.to.shared.u64 t, %1; cvt.u32.u64 %0, t; }" : "=r"(a) : "l"(p));
    return a;
}
__device__ __forceinline__ void cp_async16(uint32_t dst, const void* src, bool pred) {
    int sz = pred ? 16 : 0;
    asm volatile("cp.async.cg.shared.global [%0], [%1], 16, %2;"
                 :: "r"(dst), "l"(src), "r"(sz) : "memory");
}
__device__ __forceinline__ void cp_commit() {
    asm volatile("cp.async.commit_group;" ::: "memory");
}
template <int NW>
__device__ __forceinline__ void cp_wait_group() {
    asm volatile("cp.async.wait_group %0;" :: "n"(NW) : "memory");
}
// pack two floats -> bf16x2 (low half = v0), return residuals
__device__ __forceinline__ uint32_t bf16pack_r(float v0, float v1, float& r0, float& r1) {
    __nv_bfloat16 h0 = __float2bfloat16(v0);
    __nv_bfloat16 h1 = __float2bfloat16(v1);
    r0 = v0 - __bfloat162float(h0);
    r1 = v1 - __bfloat162float(h1);
    return ((uint32_t)__bfloat16_as_ushort(h1) << 16) | (uint32_t)__bfloat16_as_ushort(h0);
}
__device__ __forceinline__ uint32_t bf16pack(float v0, float v1) {
    __nv_bfloat162 t = __floats2bfloat162_rn(v0, v1);
    return *(uint32_t*)&t;
}

// ---------------- prep ----------------
__global__ void zero_pre_kernel(int N, int G) {
    int i = blockIdx.x * blockDim.x + threadIdx.x;
    if (i < G * 32) *(float4*)&g_sums[(size_t)i * 4] = make_float4(0.f, 0.f, 0.f, 0.f);
    if (i < N) g_deg[i] = 0;
    if (i < G) g_cnt[i] = 0.f;
}
__global__ void degcnt_kernel(const int* __restrict__ dst, const int* __restrict__ batch,
                              int E, int N) {
    int i = blockIdx.x * blockDim.x + threadIdx.x;
    if (i < E) atomicAdd(&g_deg[dst[i]], 1);
    if (i < N) atomicAdd(&g_cnt[batch[i]], 1.0f);
}

// W -> bf16 mma fragment order. For (kk, nt, lane): n = nt*8 + lane/4,
// k = kk*16 + 2*(lane&3) + {0,1} and +8. Packs: {bh0, bh1, bl0, bl1}.
__global__ void wsplit_kernel(const float* __restrict__ W1, const float* __restrict__ W2) {
    int i = blockIdx.x * blockDim.x + threadIdx.x;
    if (i >= 2 * 4096) return;
    int conv = i >> 12;
    int idx = i & 4095;
    int lane = idx & 31, nt = (idx >> 5) & 15, kk = idx >> 9;   // kk 0..7
    int g = lane >> 2, tg = lane & 3;
    int n = nt * 8 + g;
    int k0 = kk * 16 + 2 * tg;
    const float* W = conv ? W2 : W1;
    float v00 = W[(size_t)k0 * 128 + n];
    float v01 = W[(size_t)(k0 + 1) * 128 + n];
    float v10 = W[(size_t)(k0 + 8) * 128 + n];
    float v11 = W[(size_t)(k0 + 9) * 128 + n];
    float r00, r01, r10, r11;
    uint32_t bh0 = bf16pack_r(v00, v01, r00, r01);
    uint32_t bh1 = bf16pack_r(v10, v11, r10, r11);
    uint32_t bl0 = bf16pack(r00, r01);
    uint32_t bl1 = bf16pack(r10, r11);
    uint4 o = make_uint4(bh0, bh1, bl0, bl1);
    if (conv) g_wbuf2[idx] = o; else g_wbuf1[idx] = o;
}

// ---------------- scan (deg -> rowptr/cursor/dinv) ----------------
__global__ void scan1_kernel(int N) {
    int i = blockIdx.x * 256 + threadIdx.x;
    int v = (i < N) ? g_deg[i] : 0;
    int lane = threadIdx.x & 31, w = threadIdx.x >> 5;
    int s = v;
    #pragma unroll
    for (int o = 1; o < 32; o <<= 1) {
        int t = __shfl_up_sync(0xffffffffu, s, o);
        if (lane >= o) s += t;
    }
    __shared__ int wsum[8];
    if (lane == 31) wsum[w] = s;
    __syncthreads();
    if (w == 0) {
        int ss = (lane < 8) ? wsum[lane] : 0;
        #pragma unroll
        for (int o = 1; o < 8; o <<= 1) {
            int u = __shfl_up_sync(0xffffffffu, ss, o);
            if (lane >= o) ss += u;
        }
        if (lane < 8) wsum[lane] = ss;
    }
    __syncthreads();
    s += (w > 0) ? wsum[w - 1] : 0;
    if (i < N) g_scan[i] = s;
    if (threadIdx.x == 255) g_bsum[blockIdx.x] = s;
}

__global__ void scan2_kernel(int nb) {
    int t = threadIdx.x;                     // 512 threads
    int v = (t < nb) ? g_bsum[t] : 0;
    int lane = t & 31, w = t >> 5;
    int s = v;
    #pragma unroll
    for (int o = 1; o < 32; o <<= 1) {
        int u = __shfl_up_sync(0xffffffffu, s, o);
        if (lane >= o) s += u;
    }
    __shared__ int wsum[16];
    if (lane == 31) wsum[w] = s;
    __syncthreads();
    if (w == 0) {
        int ss = (lane < 16) ? wsum[lane] : 0;
        #pragma unroll
        for (int o = 1; o < 16; o <<= 1) {
            int u = __shfl_up_sync(0xffffffffu, ss, o);
            if (lane >= o) ss += u;
        }
        if (lane < 16) wsum[lane] = ss;
    }
    __syncthreads();
    s += (w > 0) ? wsum[w - 1] : 0;
    if (t < nb) g_boff[t] = s;
}

__global__ void scan3_kernel(int N) {
    int i = blockIdx.x * blockDim.x + threadIdx.x;
    if (i >= N) return;
    int b = i >> 8;
    int incl = ((b > 0) ? g_boff[b - 1] : 0) + g_scan[i];
    g_rowptr[i + 1] = incl;
    g_cursor[i] = incl - g_deg[i];
    g_dinv[i] = rsqrtf((float)g_deg[i] + 1.0f);
    if (i == 0) g_rowptr[0] = 0;
}

__global__ void scatter_kernel(const int* __restrict__ src, const int* __restrict__ dst, int E) {
    int e = blockIdx.x * blockDim.x + threadIdx.x;
    if (e >= E) return;
    int d = dst[e];
    int s = src[e];
    int pos = atomicAdd(&g_cursor[d], 1);
    g_es[pos] = s;
    g_enorm[pos] = g_dinv[s] * g_dinv[d];
}

// ---------------- tensor GEMM: C[M,128] = A[M,128] @ W (3xBF16, fragment-order W) --------
static constexpr int SM_WS_BYTES = 4096 * 16;          // 65536
static constexpr int AS_STRIDE   = 148;                // floats; 148 % 32 = 20 -> <=2-way
static constexpr int SM_GEMM_TOTAL = SM_WS_BYTES + 128 * AS_STRIDE * 4;  // 141312

__global__ __launch_bounds__(256, 1) void gemm_tc_kernel(
    const float* __restrict__ A, const uint4* __restrict__ Wbuf,
    float* __restrict__ C, int M)
{
    extern __shared__ char smem[];
    uint4* Ws = (uint4*)smem;
    float* As = (float*)(smem + SM_WS_BYTES);
    uint32_t ws_b = smem_u32(Ws), as_b = smem_u32(As);

    int tid = threadIdx.x, wid = tid >> 5, lane = tid & 31;
    int g = lane >> 2, tg = lane & 3;
    int wm = wid & 1, wn = wid >> 1;         // warp tile: m64 x n32
    int row0 = blockIdx.x * 128;

    // W: 4096 uint4, 16 per thread (group 0 with A chunk 0)
    #pragma unroll
    for (int it = 0; it < 16; it++) {
        int idx = it * 256 + tid;
        cp_async16(ws_b + idx * 16, Wbuf + idx, true);
    }
    // A chunks: per kc, 1024 float4 (128 rows x 8 float4)
    #pragma unroll
    for (int kc = 0; kc < 4; kc++) {
        #pragma unroll
        for (int it = 0; it < 4; it++) {
            int j = it * 256 + tid;          // 0..1023
            int r = j >> 3, c4 = j & 7;
            int col = kc * 32 + c4 * 4;
            bool pred = (row0 + r) < M;
            int r_eff = pred ? (row0 + r) : 0;
            cp_async16(as_b + (r * AS_STRIDE + col) * 4, A + (size_t)r_eff * 128 + col, pred);
        }
        cp_commit();                          // groups: G0=W+A0, G1=A1, G2=A2, G3=A3
    }

    float acc[4][4][4];
    #pragma unroll
    for (int mi = 0; mi < 4; mi++)
        #pragma unroll
        for (int ni = 0; ni < 4; ni++)
            #pragma unroll
            for (int j = 0; j < 4; j++) acc[mi][ni][j] = 0.f;

    #pragma unroll
    for (int kc = 0; kc < 4; kc++) {
        if      (kc == 0) cp_wait_group<3>();
        else if (kc == 1) cp_wait_group<2>();
        else if (kc == 2) cp_wait_group<1>();
        else              cp_wait_group<0>();
        __syncthreads();

        #pragma unroll
        for (int k0 = 0; k0 < 2; k0++) {      // two k16 steps per 32-wide chunk
            int kstep = kc * 2 + k0;          // 0..7
            int kb2 = kc * 32 + k0 * 16 + 2 * tg;
            // A fragments: split fp32 -> bf16 hi + bf16 residual at load time
            uint32_t ah[4][4], al[4][4];
            #pragma unroll
            for (int mi = 0; mi < 4; mi++) {
                int r = wm * 64 + mi * 16 + g;
                float2 p0 = *(float2*)&As[r * AS_STRIDE + kb2];
                float2 p1 = *(float2*)&As[(r + 8) * AS_STRIDE + kb2];
                float2 p2 = *(float2*)&As[r * AS_STRIDE + kb2 + 8];
                float2 p3 = *(float2*)&As[(r + 8) * AS_STRIDE + kb2 + 8];
                float r0, r1;
                ah[mi][0] = bf16pack_r(p0.x, p0.y, r0, r1); al[mi][0] = bf16pack(r0, r1);
                ah[mi][1] = bf16pack_r(p1.x, p1.y, r0, r1); al[mi][1] = bf16pack(r0, r1);
                ah[mi][2] = bf16pack_r(p2.x, p2.y, r0, r1); al[mi][2] = bf16pack(r0, r1);
                ah[mi][3] = bf16pack_r(p3.x, p3.y, r0, r1); al[mi][3] = bf16pack(r0, r1);
            }
            // B fragments: one LDS.128 each; 3-term mma
            #pragma unroll
            for (int ni = 0; ni < 4; ni++) {
                int nt = wn * 4 + ni;
                uint4 w4 = Ws[kstep * 512 + nt * 32 + lane];
                uint32_t bh[2] = { w4.x, w4.y };
                uint32_t bl[2] = { w4.z, w4.w };
                #pragma unroll
                for (int mi = 0; mi < 4; mi++) {
                    mma_bf16(acc[mi][ni], ah[mi], bh);
                    mma_bf16(acc[mi][ni], ah[mi], bl);
                    mma_bf16(acc[mi][ni], al[mi], bh);
                }
            }
        }
        __syncthreads();
    }

    // epilogue
    #pragma unroll
    for (int mi = 0; mi < 4; mi++) {
        int r0 = row0 + wm * 64 + mi * 16 + g;
        int r1 = r0 + 8;
        #pragma unroll
        for (int ni = 0; ni < 4; ni++) {
            int col = wn * 32 + ni * 8 + tg * 2;
            if (r0 < M) *(float2*)&C[(size_t)r0 * 128 + col] = make_float2(acc[mi][ni][0], acc[mi][ni][1]);
            if (r1 < M) *(float2*)&C[(size_t)r1 * 128 + col] = make_float2(acc[mi][ni][2], acc[mi][ni][3]);
        }
    }
}

// ---------------- CSR aggregation (fused epilogue) ----------------
template <bool POOL>
__global__ void agg_kernel(const float* __restrict__ xw, const float* __restrict__ bias,
                           float* __restrict__ hout, const int* __restrict__ batch, int N)
{
    int d = (blockIdx.x * blockDim.x + threadIdx.x) >> 5;
    int lane = threadIdx.x & 31;
    if (d >= N) return;

    float di = g_dinv[d];
    float sl = di * di;
    float4 acc = *(const float4*)&xw[(size_t)d * 128 + lane * 4];
    acc.x *= sl; acc.y *= sl; acc.z *= sl; acc.w *= sl;

    int e0 = g_rowptr[d], e1 = g_rowptr[d + 1];
    int e = e0;
    for (; e + 4 <= e1; e += 4) {
        int s0 = g_es[e], s1 = g_es[e + 1], s2 = g_es[e + 2], s3 = g_es[e + 3];
        float n0 = g_enorm[e], n1 = g_enorm[e + 1];
        float n2 = g_enorm[e + 2], n3 = g_enorm[e + 3];
        float4 v0 = *(const float4*)&xw[(size_t)s0 * 128 + lane * 4];
        float4 v1 = *(const float4*)&xw[(size_t)s1 * 128 + lane * 4];
        float4 v2 = *(const float4*)&xw[(size_t)s2 * 128 + lane * 4];
        float4 v3 = *(const float4*)&xw[(size_t)s3 * 128 + lane * 4];
        acc.x = fmaf(v0.x, n0, fmaf(v1.x, n1, fmaf(v2.x, n2, fmaf(v3.x, n3, acc.x))));
        acc.y = fmaf(v0.y, n0, fmaf(v1.y, n1, fmaf(v2.y, n2, fmaf(v3.y, n3, acc.y))));
        acc.z = fmaf(v0.z, n0, fmaf(v1.z, n1, fmaf(v2.z, n2, fmaf(v3.z, n3, acc.z))));
        acc.w = fmaf(v0.w, n0, fmaf(v1.w, n1, fmaf(v2.w, n2, fmaf(v3.w, n3, acc.w))));
    }
    for (; e < e1; e++) {
        int s = g_es[e];
        float nm = g_enorm[e];
        float4 v = *(const float4*)&xw[(size_t)s * 128 + lane * 4];
        acc.x = fmaf(v.x, nm, acc.x);
        acc.y = fmaf(v.y, nm, acc.y);
        acc.z = fmaf(v.z, nm, acc.z);
        acc.w = fmaf(v.w, nm, acc.w);
    }

    float4 b = *(const float4*)&bias[lane * 4];
    acc.x += b.x; acc.y += b.y; acc.z += b.z; acc.w += b.w;

    if (POOL) {
        int gi = batch[d];
        red_add_v4(&g_sums[(size_t)gi * 128 + lane * 4], acc);
    } else {
        acc.x = fmaxf(acc.x, 0.f); acc.y = fmaxf(acc.y, 0.f);
        acc.z = fmaxf(acc.z, 0.f); acc.w = fmaxf(acc.w, 0.f);
        *(float4*)&hout[(size_t)d * 128 + lane * 4] = acc;
    }
}

// ---------------- GRU step (h0=0) + relu + layernorm + linear head ----------------
__global__ __launch_bounds__(128) void gru_ln_out_kernel(
    const float* __restrict__ W_ih, const float* __restrict__ b_ih,
    const float* __restrict__ b_hh, const float* __restrict__ W_lin,
    const float* __restrict__ b_lin, float* __restrict__ out)
{
    int g = blockIdx.x;
    int tid = threadIdx.x;
    int lane = tid & 31, w = tid >> 5;

    __shared__ float gs[128];
    __shared__ float gi[384];
    __shared__ float rbuf1[4], rbuf2[4];

    float cnt = fmaxf(g_cnt[g], 1.0f);
    gs[tid] = g_sums[(size_t)g * 128 + tid] / cnt;
    __syncthreads();

    for (int j = w; j < 384; j += 4) {
        const float* wr = W_ih + (size_t)j * 128;
        float s = 0.f;
        #pragma unroll
        for (int t = 0; t < 4; t++) {
            int k = lane + t * 32;
            s += gs[k] * wr[k];
        }
        #pragma unroll
        for (int o = 16; o > 0; o >>= 1) s += __shfl_xor_sync(0xffffffffu, s, o);
        if (lane == 0) gi[j] = s + b_ih[j];
    }
    __syncthreads();

    float r  = 1.f / (1.f + expf(-(gi[tid]       + b_hh[tid])));
    float z  = 1.f / (1.f + expf(-(gi[tid + 128] + b_hh[tid + 128])));
    float nn = tanhf(gi[tid + 256] + r * b_hh[tid + 256]);
    float v  = fmaxf((1.f - z) * nn, 0.f);

    float s1 = v, s2 = v * v;
    #pragma unroll
    for (int o = 16; o > 0; o >>= 1) {
        s1 += __shfl_xor_sync(0xffffffffu, s1, o);
        s2 += __shfl_xor_sync(0xffffffffu, s2, o);
    }
    if (lane == 0) { rbuf1[w] = s1; rbuf2[w] = s2; }
    __syncthreads();
    float S1 = rbuf1[0] + rbuf1[1] + rbuf1[2] + rbuf1[3];
    float S2 = rbuf2[0] + rbuf2[1] + rbuf2[2] + rbuf2[3];
    float mu  = S1 * (1.f / 128.f);
    float var = S2 * (1.f / 128.f) - mu * mu;
    float y = (v - mu) * rsqrtf(var + 1e-5f);

    float p = y * W_lin[tid];
    #pragma unroll
    for (int o = 16; o > 0; o >>= 1) p += __shfl_xor_sync(0xffffffffu, p, o);
    __syncthreads();
    if (lane == 0) rbuf1[w] = p;
    __syncthreads();
    if (tid == 0) out[g] = rbuf1[0] + rbuf1[1] + rbuf1[2] + rbuf1[3] + b_lin[0];
}

// ---------------- launch ----------------
extern "C" void kernel_launch(void* const* d_in, const int* in_sizes, int n_in,
                              void* d_out, int out_size)
{
    const float* x     = (const float*)d_in[0];
    const int*   ei    = (const int*)  d_in[1];
    const int*   batch = (const int*)  d_in[2];
    const float* W1    = (const float*)d_in[3];
    const float* b1    = (const float*)d_in[4];
    const float* W2    = (const float*)d_in[5];
    const float* b2    = (const float*)d_in[6];
    const float* W_ih  = (const float*)d_in[7];
    /* W_hh = d_in[8] unused: h0 == 0 */
    const float* b_ih  = (const float*)d_in[9];
    const float* b_hh  = (const float*)d_in[10];
    const float* W_lin = (const float*)d_in[11];
    const float* b_lin = (const float*)d_in[12];
    float* out = (float*)d_out;

    const int N = in_sizes[0] / 128;
    const int E = in_sizes[1] / 2;
    const int G = out_size;
    const int* srcp = ei;
    const int* dstp = ei + E;

    float *p_xw, *p_h;
    uint4 *p_wb1, *p_wb2;
    cudaGetSymbolAddress((void**)&p_xw,  g_xw);
    cudaGetSymbolAddress((void**)&p_h,   g_h);
    cudaGetSymbolAddress((void**)&p_wb1, g_wbuf1);
    cudaGetSymbolAddress((void**)&p_wb2, g_wbuf2);

    static cudaStream_t s_side = nullptr;
    static cudaEvent_t ev_fork = nullptr, ev_join = nullptr;
    if (!s_side) {
        cudaFuncSetAttribute(gemm_tc_kernel,
                             cudaFuncAttributeMaxDynamicSharedMemorySize, SM_GEMM_TOTAL);
        cudaStreamCreateWithFlags(&s_side, cudaStreamNonBlocking);
        cudaEventCreateWithFlags(&ev_fork, cudaEventDisableTiming);
        cudaEventCreateWithFlags(&ev_join, cudaEventDisableTiming);
    }

    const int T = 256;
    int bN   = (N + T - 1) / T;
    int bE   = (E + T - 1) / T;
    int nz   = (N > G * 32) ? N : G * 32;
    int bZ   = (nz + T - 1) / T;
    int nb   = (N + 255) / 256;
    long long wthreads = (long long)N * 32;
    int bAgg = (int)((wthreads + T - 1) / T);
    int bGemm = (N + 127) / 128;

    // fork: CSR build on side stream, GEMM path on main stream
    cudaEventRecord(ev_fork, 0);
    cudaStreamWaitEvent(s_side, ev_fork, 0);

    zero_pre_kernel<<<bZ, T, 0, s_side>>>(N, G);
    degcnt_kernel<<<bE, T, 0, s_side>>>(dstp, batch, E, N);
    scan1_kernel<<<nb, 256, 0, s_side>>>(N);
    scan2_kernel<<<1, 512, 0, s_side>>>(nb);
    scan3_kernel<<<bN, T, 0, s_side>>>(N);
    scatter_kernel<<<bE, T, 0, s_side>>>(srcp, dstp, E);
    cudaEventRecord(ev_join, s_side);

    // main stream: weight split + GEMM1 overlap the CSR build
    wsplit_kernel<<<(2 * 4096 + T - 1) / T, T>>>(W1, W2);
    gemm_tc_kernel<<<bGemm, 256, SM_GEMM_TOTAL>>>(x, p_wb1, p_xw, N);

    cudaStreamWaitEvent(0, ev_join, 0);

    // conv1 aggregate, conv2, pool
    agg_kernel<false><<<bAgg, T>>>(p_xw, b1, p_h, batch, N);
    gemm_tc_kernel<<<bGemm, 256, SM_GEMM_TOTAL>>>(p_h, p_wb2, p_xw, N);
    agg_kernel<true><<<bAgg, T>>>(p_xw, b2, nullptr, batch, N);

    // GRU + LN + head
    gru_ln_out_kernel<<<G, 128>>>(W_ih, b_ih, b_hh, W_lin, b_lin, out);
}